// round 10
// baseline (speedup 1.0000x reference)
#include <cuda_runtime.h>
#include <math.h>
#include <stdint.h>

#define NB 2
#define NS 2048
#define NHQ 32
#define NHK 8
#define ND 128
#define NG 4
#define WIN 1024

__device__ float g_kr[(size_t)NB * NHK * NS * ND];
__device__ float g_vr[(size_t)NB * NHK * NS * ND];

__device__ __forceinline__ float ex2f(float x) {
    float r; asm("ex2.approx.ftz.f32 %0,%1;" : "=f"(r) : "f"(x)); return r;
}
__device__ __forceinline__ uint32_t f2tf(float x) {
    uint32_t r; asm("cvt.rna.tf32.f32 %0,%1;" : "=r"(r) : "f"(x)); return r;
}
__device__ __forceinline__ void mma_tf32(float* d, const uint32_t* a, const uint32_t* b) {
    asm volatile(
        "mma.sync.aligned.m16n8k8.row.col.f32.tf32.tf32.f32 "
        "{%0,%1,%2,%3},{%4,%5,%6,%7},{%8,%9},{%0,%1,%2,%3};"
        : "+f"(d[0]), "+f"(d[1]), "+f"(d[2]), "+f"(d[3])
        : "r"(a[0]), "r"(a[1]), "r"(a[2]), "r"(a[3]), "r"(b[0]), "r"(b[1]));
}
__device__ __forceinline__ uint32_t cvta(const void* p) {
    return (uint32_t)__cvta_generic_to_shared(p);
}
__device__ __forceinline__ void cpa(uint32_t d, const float* s) {
    asm volatile("cp.async.cg.shared.global [%0],[%1],16;" :: "r"(d), "l"(s));
}
#define COMMIT() asm volatile("cp.async.commit_group;")
#define WAITALL() asm volatile("cp.async.wait_group 0;")
#define BARP(id) asm volatile("bar.sync %0, 64;" :: "r"(id) : "memory")

// smem float offsets
#define QS_OFF 0        /* 64x132 Q tf32 staging (prologue only) */
#define KH_OFF 8448     /* + buf*8448 */
#define V_OFF  25344    /* + buf*8448 */
#define PS_OFF 42240    /* 64x68: sincos table / P tile */
#define ML_OFF 46592    /* [0:128) half maxes, [128:256) half lsums */
#define SMEM_FLOATS 46848

// ---------------------------------------------------------------------------
__global__ void prep_kernel(const float* __restrict__ key,
                            const float* __restrict__ value,
                            const int* __restrict__ pos) {
    const int k0 = blockIdx.x * 64, hk = blockIdx.y, b = blockIdx.z;
    const int tid = threadIdx.x;
#pragma unroll
    for (int i = 0; i < 16; i++) {
        int idx = tid + i * 256;
        int kl = idx >> 6, dp = idx & 63;
        int token = b * NS + k0 + kl;
        float ps = (float)pos[token];
        float invf = powf(10000.0f, -((float)dp) / 64.0f);
        float sn, cs; sincosf(ps * invf, &sn, &cs);
        const float* kp = key + (size_t)token * (NHK * ND) + hk * ND;
        float x1 = kp[dp], x2 = kp[dp + 64];
        size_t ob = ((size_t)(b * NHK + hk) * NS + k0 + kl) * ND;
        g_kr[ob + dp]      = __uint_as_float(f2tf(x1 * cs - x2 * sn));
        g_kr[ob + dp + 64] = __uint_as_float(f2tf(x2 * cs + x1 * sn));
    }
#pragma unroll
    for (int i = 0; i < 8; i++) {
        int idx = tid + i * 256;
        int kl = idx >> 5, c4 = (idx & 31) * 4;
        int token = b * NS + k0 + kl;
        float4 v4 = *(const float4*)(value + (size_t)token * (NHK * ND) + hk * ND + c4);
        float4 o;
        o.x = __uint_as_float(f2tf(v4.x));
        o.y = __uint_as_float(f2tf(v4.y));
        o.z = __uint_as_float(f2tf(v4.z));
        o.w = __uint_as_float(f2tf(v4.w));
        *(float4*)(g_vr + ((size_t)(b * NHK + hk) * NS + k0 + kl) * ND + c4) = o;
    }
}

// ---------------------------------------------------------------------------
// attention: block = (16 queries, hk, b); 8 warps: h=w&3 (head), kh=w>>2.
// QK: warp (h,kh) does rows of h x keys kh*32..+31 (Q in regs).
// PV: warp (h,kh) does rows of h x dims kh*64..+63 over all 64 keys.
// Pair (h,0)/(h,1) exchanges via bar.sync h+1.
// ---------------------------------------------------------------------------
__global__ void __launch_bounds__(256, 1)
attn_kernel(const float* __restrict__ query, const int* __restrict__ pos,
            float* __restrict__ out) {
    extern __shared__ float smf[];
    uint32_t* QH = (uint32_t*)(smf + QS_OFF);
    float*    Ps = smf + PS_OFF;
    float*    ML = smf + ML_OFF;

    const int qt = blockIdx.x, hk = blockIdx.y, b = blockIdx.z;
    const int q0 = qt * 16, tid = threadIdx.x;
    const int w = tid >> 5, lane = tid & 31;
    const int h = w & 3, kh = w >> 2;
    const int lr = lane >> 2, lc = lane & 3;
    const int bid = h + 1;
    const float CF = 1.4426950408889634f * 0.08838834764831845f;

    int jmin = q0 - (WIN - 1); if (jmin < 0) jmin = 0; jmin &= ~63;
    const int nt = (q0 + 15 - jmin) / 64 + 1;
    const float* kb = g_kr + (size_t)(b * NHK + hk) * NS * ND;
    const float* vb = g_vr + (size_t)(b * NHK + hk) * NS * ND;
    const int cr = tid >> 5, cc4 = (tid & 31) * 4;

    // tile 0 copies first (overlap DRAM with rope math)
#pragma unroll
    for (int i = 0; i < 8; i++) {
        cpa(cvta(smf + KH_OFF + (cr + i * 8) * 132 + cc4), kb + (size_t)(jmin + cr + i * 8) * ND + cc4);
        cpa(cvta(smf + V_OFF  + (cr + i * 8) * 132 + cc4), vb + (size_t)(jmin + cr + i * 8) * ND + cc4);
    }
    COMMIT();

    // sincos table (in Ps)
#pragma unroll
    for (int i = 0; i < 4; i++) {
        int idx = tid + i * 256;
        int qi = idx >> 6, dp = idx & 63;
        float ps = (float)pos[b * NS + q0 + qi];
        float invf = powf(10000.0f, -((float)dp) / 64.0f);
        float sn, cs; sincosf(ps * invf, &sn, &cs);
        Ps[idx] = cs; Ps[1024 + idx] = sn;
    }
    __syncthreads();
    // rope + scale + round Q -> QH staging
#pragma unroll
    for (int i = 0; i < 16; i++) {
        int idx = tid + i * 256;
        int row = idx >> 6, dp = idx & 63;
        int qi = row & 15, hh = row >> 4;
        const float* qp = query + ((size_t)(b * NS + q0 + qi) * NHQ + (hk * NG + hh)) * ND;
        float x1 = qp[dp], x2 = qp[dp + 64];
        float cs = Ps[qi * 64 + dp], sn = Ps[1024 + qi * 64 + dp];
        QH[row * 132 + dp]      = f2tf((x1 * cs - x2 * sn) * CF);
        QH[row * 132 + dp + 64] = f2tf((x2 * cs + x1 * sn) * CF);
    }
    __syncthreads();

    // hoist Q fragments to registers
    uint32_t qf[64];
#pragma unroll
    for (int c = 0; c < 16; c++) {
        qf[c * 4 + 0] = QH[(h * 16 + lr) * 132 + c * 8 + lc];
        qf[c * 4 + 1] = QH[(h * 16 + lr + 8) * 132 + c * 8 + lc];
        qf[c * 4 + 2] = QH[(h * 16 + lr) * 132 + c * 8 + lc + 4];
        qf[c * 4 + 3] = QH[(h * 16 + lr + 8) * 132 + c * 8 + lc + 4];
    }

    float oacc[8][4];
#pragma unroll
    for (int nb = 0; nb < 8; nb++)
#pragma unroll
        for (int e = 0; e < 4; e++) oacc[nb][e] = 0.0f;
    float mcur0 = -1e30f, mcur1 = -1e30f, lcur0 = 0.0f, lcur1 = 0.0f;

    const int row0 = h * 16 + lr, row1 = row0 + 8;
    const int i0 = q0 + lr, i1 = i0 + 8;

    for (int t = 0; t < nt; t++) {
        const int k0 = jmin + t * 64, buf = t & 1;

        WAITALL();         // tile t resident
        __syncthreads();   // all warps past prior tile's reads

        // issue prefetch of t+1 AFTER the sync (other buffer now reusable)
        if (t + 1 < nt) {
            const float* ks = kb + (size_t)(k0 + 64) * ND;
            const float* vs = vb + (size_t)(k0 + 64) * ND;
            uint32_t kd = cvta(smf + KH_OFF + (1 - buf) * 8448);
            uint32_t vd = cvta(smf + V_OFF  + (1 - buf) * 8448);
#pragma unroll
            for (int i = 0; i < 8; i++) {
                cpa(kd + ((cr + i * 8) * 132 + cc4) * 4, ks + (size_t)(cr + i * 8) * ND + cc4);
                cpa(vd + ((cr + i * 8) * 132 + cc4) * 4, vs + (size_t)(cr + i * 8) * ND + cc4);
            }
            COMMIT();
        }

        const uint32_t* KH = (const uint32_t*)(smf + KH_OFF + buf * 8448);
        const uint32_t* Vu = (const uint32_t*)(smf + V_OFF  + buf * 8448);

        // ---- QK^T (Q regs x K smem), warp covers keys kh*32..+31 ----
        float sacc[4][4];
#pragma unroll
        for (int nb = 0; nb < 4; nb++)
#pragma unroll
            for (int e = 0; e < 4; e++) sacc[nb][e] = 0.0f;
#pragma unroll
        for (int c = 0; c < 16; c++) {
#pragma unroll
            for (int nb = 0; nb < 4; nb++) {
                int krow = kh * 32 + nb * 8 + lr;
                uint32_t bh[2];
                bh[0] = KH[krow * 132 + c * 8 + lc];
                bh[1] = KH[krow * 132 + c * 8 + lc + 4];
                mma_tf32(sacc[nb], qf + c * 4, bh);
            }
        }

        // ---- mask ----
        if (!((k0 + 63 <= q0) && (q0 + 15 - k0 < WIN))) {
#pragma unroll
            for (int nb = 0; nb < 4; nb++) {
                int j0 = k0 + kh * 32 + nb * 8 + 2 * lc;
                if (j0 > i0     || i0 - j0 >= WIN)     sacc[nb][0] = -1e38f;
                if (j0 + 1 > i0 || i0 - j0 - 1 >= WIN) sacc[nb][1] = -1e38f;
                if (j0 > i1     || i1 - j0 >= WIN)     sacc[nb][2] = -1e38f;
                if (j0 + 1 > i1 || i1 - j0 - 1 >= WIN) sacc[nb][3] = -1e38f;
            }
        }

        // ---- half-row max, exchange within pair ----
        float r0 = -1e38f, r1 = -1e38f;
#pragma unroll
        for (int nb = 0; nb < 4; nb++) {
            r0 = fmaxf(r0, fmaxf(sacc[nb][0], sacc[nb][1]));
            r1 = fmaxf(r1, fmaxf(sacc[nb][2], sacc[nb][3]));
        }
        r0 = fmaxf(r0, __shfl_xor_sync(0xffffffffu, r0, 1));
        r0 = fmaxf(r0, __shfl_xor_sync(0xffffffffu, r0, 2));
        r1 = fmaxf(r1, __shfl_xor_sync(0xffffffffu, r1, 1));
        r1 = fmaxf(r1, __shfl_xor_sync(0xffffffffu, r1, 2));
        if (lc == 0) { ML[kh * 64 + row0] = r0; ML[kh * 64 + row1] = r1; }
        BARP(bid);
        float rm0 = fmaxf(ML[row0], ML[64 + row0]);
        float rm1 = fmaxf(ML[row1], ML[64 + row1]);

        // ---- softmax with global row max ----
        float mn0 = fmaxf(mcur0, rm0), mn1 = fmaxf(mcur1, rm1);
        float f0 = ex2f(mcur0 - mn0), f1 = ex2f(mcur1 - mn1);
        mcur0 = mn0; mcur1 = mn1;
        lcur0 *= f0; lcur1 *= f1;
        float s0 = 0.0f, s1 = 0.0f;
#pragma unroll
        for (int nb = 0; nb < 4; nb++) {
            float p00 = ex2f(sacc[nb][0] - mn0), p01 = ex2f(sacc[nb][1] - mn0);
            float p10 = ex2f(sacc[nb][2] - mn1), p11 = ex2f(sacc[nb][3] - mn1);
            s0 += p00 + p01; s1 += p10 + p11;
            int col = kh * 32 + nb * 8 + 2 * lc;
            *(float2*)&Ps[row0 * 68 + col] = make_float2(p00, p01);
            *(float2*)&Ps[row1 * 68 + col] = make_float2(p10, p11);
        }
        lcur0 += s0; lcur1 += s1;
#pragma unroll
        for (int nb = 0; nb < 8; nb++) {
            oacc[nb][0] *= f0; oacc[nb][1] *= f0;
            oacc[nb][2] *= f1; oacc[nb][3] *= f1;
        }
        BARP(bid);   // both halves of P(head h) ready

        // ---- P @ V, warp covers dims kh*64..+63, all 64 keys ----
#pragma unroll
        for (int kc = 0; kc < 8; kc++) {
            uint32_t ap[4];
            ap[0] = f2tf(Ps[row0 * 68 + kc * 8 + lc]);
            ap[1] = f2tf(Ps[row1 * 68 + kc * 8 + lc]);
            ap[2] = f2tf(Ps[row0 * 68 + kc * 8 + lc + 4]);
            ap[3] = f2tf(Ps[row1 * 68 + kc * 8 + lc + 4]);
#pragma unroll
            for (int nb = 0; nb < 8; nb++) {
                uint32_t bv[2];
                bv[0] = Vu[(kc * 8 + lc) * 132 + kh * 64 + nb * 8 + lr];
                bv[1] = Vu[(kc * 8 + lc + 4) * 132 + kh * 64 + nb * 8 + lr];
                mma_tf32(oacc[nb], ap, bv);
            }
        }
        // no end sync: next iter's WAITALL+syncthreads orders reuse
    }

    // ---- epilogue: merge l within pair, write own dims directly ----
    lcur0 += __shfl_xor_sync(0xffffffffu, lcur0, 1);
    lcur0 += __shfl_xor_sync(0xffffffffu, lcur0, 2);
    lcur1 += __shfl_xor_sync(0xffffffffu, lcur1, 1);
    lcur1 += __shfl_xor_sync(0xffffffffu, lcur1, 2);
    if (lc == 0) { ML[128 + kh * 64 + row0] = lcur0; ML[128 + kh * 64 + row1] = lcur1; }
    BARP(bid);
    float li0 = 1.0f / (ML[128 + row0] + ML[192 + row0]);
    float li1 = 1.0f / (ML[128 + row1] + ML[192 + row1]);

    float* ob0 = out + ((size_t)(b * NS + q0 + lr) * NHQ + hk * NG + h) * ND + kh * 64;
    float* ob1 = out + ((size_t)(b * NS + q0 + lr + 8) * NHQ + hk * NG + h) * ND + kh * 64;
#pragma unroll
    for (int nb = 0; nb < 8; nb++) {
        int col = nb * 8 + 2 * lc;
        *(float2*)&ob0[col] = make_float2(oacc[nb][0] * li0, oacc[nb][1] * li0);
        *(float2*)&ob1[col] = make_float2(oacc[nb][2] * li1, oacc[nb][3] * li1);
    }
}

// ---------------------------------------------------------------------------
extern "C" void kernel_launch(void* const* d_in, const int* in_sizes, int n_in,
                              void* d_out, int out_size) {
    const float* q   = (const float*)d_in[0];
    const float* k   = (const float*)d_in[1];
    const float* v   = (const float*)d_in[2];
    const int*   pos = (const int*)d_in[3];
    float* out = (float*)d_out;

    dim3 gp(NS / 64, NHK, NB);
    prep_kernel<<<gp, 256>>>(k, v, pos);

    const int smem = SMEM_FLOATS * 4;
    cudaFuncSetAttribute(attn_kernel,
                         cudaFuncAttributeMaxDynamicSharedMemorySize, smem);
    dim3 ga(NS / 16, NHK, NB);
    attn_kernel<<<ga, 256, smem>>>(q, pos, out);
}

// round 12
// speedup vs baseline: 1.3619x; 1.3619x over previous
#include <cuda_runtime.h>
#include <math.h>
#include <stdint.h>

#define NB 2
#define NS 2048
#define NHQ 32
#define NHK 8
#define ND 128
#define NG 4
#define WIN 1024
#define NTILES 32

// fragment-packed per-64-key tiles: [b][hk][tile][8192]
__device__ float g_kt[(size_t)NB * NHK * NTILES * 8192];
__device__ float g_vt[(size_t)NB * NHK * NTILES * 8192];

__device__ __forceinline__ float ex2f(float x) {
    float r; asm("ex2.approx.ftz.f32 %0,%1;" : "=f"(r) : "f"(x)); return r;
}
__device__ __forceinline__ uint32_t f2tf(float x) {
    uint32_t r; asm("cvt.rna.tf32.f32 %0,%1;" : "=r"(r) : "f"(x)); return r;
}
__device__ __forceinline__ void mma_tf32(float* d, const uint32_t* a, const uint32_t* b) {
    asm volatile(
        "mma.sync.aligned.m16n8k8.row.col.f32.tf32.tf32.f32 "
        "{%0,%1,%2,%3},{%4,%5,%6,%7},{%8,%9},{%0,%1,%2,%3};"
        : "+f"(d[0]), "+f"(d[1]), "+f"(d[2]), "+f"(d[3])
        : "r"(a[0]), "r"(a[1]), "r"(a[2]), "r"(a[3]), "r"(b[0]), "r"(b[1]));
}
__device__ __forceinline__ uint32_t cvta(const void* p) {
    return (uint32_t)__cvta_generic_to_shared(p);
}
__device__ __forceinline__ void cpa(uint32_t d, const float* s) {
    asm volatile("cp.async.cg.shared.global [%0],[%1],16;" :: "r"(d), "l"(s));
}
#define COMMIT()  asm volatile("cp.async.commit_group;")
#define WAITALL() asm volatile("cp.async.wait_group 0;")

// smem float offsets
#define QF_OFF 0        /* 4h x 16c x 32lane x 4  = 8192 */
#define KF_OFF 8192     /* 2kh x 16c x 4nb x 32lane x 2 = 8192 */
#define VF_OFF 16384    /* 2kh x 8kc x 8nb x 32lane x 2 = 8192 */
#define PS_OFF 24576    /* 64 x 68; cols 64-67 = max/lsum exchange */
#define SMEM_FLOATS 28928   /* 115712 bytes; x2 CTAs = 231424 <= 227KB/SM */

// fragment index helpers (element -> packed offset within an 8192-float tile)
__device__ __forceinline__ int kfrag_idx(int kl, int d) {
    int kh = kl >> 5, krow = kl & 31, nb = krow >> 3, lr = krow & 7;
    int c = d >> 3, cc = d & 7;
    return ((((kh * 16 + c) * 4 + nb) * 32) + lr * 4 + (cc & 3)) * 2 + (cc >> 2);
}
__device__ __forceinline__ int vfrag_idx(int kl, int d) {
    int kc = kl >> 3, kk = kl & 7;
    int kh = d >> 6, nb = (d >> 3) & 7, lr = d & 7;
    return ((((kh * 8 + kc) * 8 + nb) * 32) + lr * 4 + (kk & 3)) * 2 + (kk >> 2);
}
__device__ __forceinline__ int qfrag_idx(int r, int d) {
    int h = r >> 4, rr = r & 15, cc = d & 7;
    int j = (rr >> 3) + 2 * (cc >> 2);
    return (((h * 16 + (d >> 3)) * 32) + (rr & 7) * 4 + (cc & 3)) * 4 + j;
}

// ---------------------------------------------------------------------------
__global__ void prep_kernel(const float* __restrict__ key,
                            const float* __restrict__ value,
                            const int* __restrict__ pos) {
    const int tile = blockIdx.x, hk = blockIdx.y, b = blockIdx.z;
    const int k0 = tile * 64, tid = threadIdx.x;
    const size_t tb = ((size_t)(b * NHK + hk) * NTILES + tile) * 8192;

    // K: rope (sincos inline) + pack
#pragma unroll
    for (int i = 0; i < 16; i++) {
        int idx = tid + i * 256;
        int kl = idx >> 6, dp = idx & 63;
        float ps = (float)pos[b * NS + k0 + kl];
        float invf = powf(10000.0f, -((float)dp) / 64.0f);
        float s, c; sincosf(ps * invf, &s, &c);
        const float* kp = key + ((size_t)(b * NS + k0 + kl) * NHK + hk) * ND;
        float x1 = kp[dp], x2 = kp[dp + 64];
        g_kt[tb + kfrag_idx(kl, dp)]      = __uint_as_float(f2tf(x1 * c - x2 * s));
        g_kt[tb + kfrag_idx(kl, dp + 64)] = __uint_as_float(f2tf(x2 * c + x1 * s));
    }
    // V: round + pack
#pragma unroll
    for (int i = 0; i < 32; i++) {
        int idx = tid + i * 256;
        int kl = idx >> 7, d = idx & 127;
        float val = value[((size_t)(b * NS + k0 + kl) * NHK + hk) * ND + d];
        g_vt[tb + vfrag_idx(kl, d)] = __uint_as_float(f2tf(val));
    }
}

// ---------------------------------------------------------------------------
// attention: block=(16q, hk, b), 256 thr, 2 CTAs/SM. warp=(h=w&3, kh=w>>2).
// QK: warp covers keys kh*32..+31. PV: warp covers dims kh*64..+63.
// ---------------------------------------------------------------------------
__global__ void __launch_bounds__(256, 2)
attn_kernel(const float* __restrict__ query, const int* __restrict__ pos,
            float* __restrict__ out) {
    extern __shared__ float smf[];
    const uint4* QF4 = (const uint4*)(smf + QF_OFF);
    const uint2* KF2 = (const uint2*)(smf + KF_OFF);
    const uint2* VF2 = (const uint2*)(smf + VF_OFF);
    float*       Ps  = smf + PS_OFF;
    uint32_t*    PsU = (uint32_t*)Ps;

    const int qt = blockIdx.x, hk = blockIdx.y, b = blockIdx.z;
    const int q0 = qt * 16, tid = threadIdx.x;
    const int w = tid >> 5, lane = tid & 31;
    const int h = w & 3, kh = w >> 2;
    const int lr = lane >> 2, lc = lane & 3;
    const float CF = 1.4426950408889634f * 0.08838834764831845f;

    int jmin = q0 - (WIN - 1); if (jmin < 0) jmin = 0; jmin &= ~63;
    const int nt = (q0 + 15 - jmin) / 64 + 1;
    const size_t kbase = (size_t)(b * NHK + hk) * NTILES * 8192;
    const uint32_t smb = cvta(smf);

    // tile 0 loads first (overlap with Q rope)
    {
        const float* ks = g_kt + kbase + (size_t)(jmin >> 6) * 8192;
        const float* vs = g_vt + kbase + (size_t)(jmin >> 6) * 8192;
#pragma unroll
        for (int i = 0; i < 8; i++) {
            cpa(smb + KF_OFF * 4 + tid * 16 + i * 4096, ks + (tid * 4 + i * 1024));
            cpa(smb + VF_OFF * 4 + tid * 16 + i * 4096, vs + (tid * 4 + i * 1024));
        }
        COMMIT();
    }

    // sincos table in Ps ([0:1024) cos, [2048:3072) sin)
#pragma unroll
    for (int i = 0; i < 4; i++) {
        int idx = tid + i * 256;
        int qi = idx >> 6, dp = idx & 63;
        float ps = (float)pos[b * NS + q0 + qi];
        float invf = powf(10000.0f, -((float)dp) / 64.0f);
        float s, c; sincosf(ps * invf, &s, &c);
        Ps[idx] = c; Ps[2048 + idx] = s;
    }
    __syncthreads();
    // rope + scale + round Q directly into fragment-packed QF
    float* QFw = smf + QF_OFF;
#pragma unroll
    for (int i = 0; i < 16; i++) {
        int idx = tid + i * 256;
        int row = idx >> 6, dp = idx & 63;
        int qi = row & 15, hh = row >> 4;
        const float* qp = query + ((size_t)(b * NS + q0 + qi) * NHQ + (hk * NG + hh)) * ND;
        float x1 = qp[dp], x2 = qp[dp + 64];
        float c = Ps[qi * 64 + dp], s = Ps[2048 + qi * 64 + dp];
        QFw[qfrag_idx(row, dp)]      = __uint_as_float(f2tf((x1 * c - x2 * s) * CF));
        QFw[qfrag_idx(row, dp + 64)] = __uint_as_float(f2tf((x2 * c + x1 * s) * CF));
    }
    WAITALL();
    __syncthreads();

    float oacc[8][4];
#pragma unroll
    for (int nb = 0; nb < 8; nb++)
#pragma unroll
        for (int e = 0; e < 4; e++) oacc[nb][e] = 0.0f;
    float mcur0 = -1e30f, mcur1 = -1e30f, lcur0 = 0.0f, lcur1 = 0.0f;

    const int row0 = h * 16 + lr, row1 = row0 + 8;
    const int i0 = q0 + lr, i1 = i0 + 8;

    for (int t = 0; t < nt; t++) {
        const int k0 = jmin + t * 64;
        if (t > 0) {
            const float* ks = g_kt + kbase + (size_t)(k0 >> 6) * 8192;
            const float* vs = g_vt + kbase + (size_t)(k0 >> 6) * 8192;
#pragma unroll
            for (int i = 0; i < 8; i++) {
                cpa(smb + KF_OFF * 4 + tid * 16 + i * 4096, ks + (tid * 4 + i * 1024));
                cpa(smb + VF_OFF * 4 + tid * 16 + i * 4096, vs + (tid * 4 + i * 1024));
            }
            COMMIT();
            WAITALL();
            __syncthreads();
        }

        // ---- QK^T ----
        float sacc[4][4];
#pragma unroll
        for (int nb = 0; nb < 4; nb++)
#pragma unroll
            for (int e = 0; e < 4; e++) sacc[nb][e] = 0.0f;
#pragma unroll
        for (int c = 0; c < 16; c++) {
            uint4 qv = QF4[(h * 16 + c) * 32 + lane];
#pragma unroll
            for (int nb = 0; nb < 4; nb++) {
                uint2 kv = KF2[((kh * 16 + c) * 4 + nb) * 32 + lane];
                mma_tf32(sacc[nb], (const uint32_t*)&qv, (const uint32_t*)&kv);
            }
        }

        // ---- mask ----
        if (!((k0 + 63 <= q0) && (q0 + 15 - k0 < WIN))) {
#pragma unroll
            for (int nb = 0; nb < 4; nb++) {
                int j0 = k0 + kh * 32 + nb * 8 + 2 * lc;
                if (j0 > i0     || i0 - j0 >= WIN)     sacc[nb][0] = -1e38f;
                if (j0 + 1 > i0 || i0 - j0 - 1 >= WIN) sacc[nb][1] = -1e38f;
                if (j0 > i1     || i1 - j0 >= WIN)     sacc[nb][2] = -1e38f;
                if (j0 + 1 > i1 || i1 - j0 - 1 >= WIN) sacc[nb][3] = -1e38f;
            }
        }

        // ---- half-row max -> exchange via Ps cols 64/65 ----
        float r0 = -1e38f, r1 = -1e38f;
#pragma unroll
        for (int nb = 0; nb < 4; nb++) {
            r0 = fmaxf(r0, fmaxf(sacc[nb][0], sacc[nb][1]));
            r1 = fmaxf(r1, fmaxf(sacc[nb][2], sacc[nb][3]));
        }
        r0 = fmaxf(r0, __shfl_xor_sync(0xffffffffu, r0, 1));
        r0 = fmaxf(r0, __shfl_xor_sync(0xffffffffu, r0, 2));
        r1 = fmaxf(r1, __shfl_xor_sync(0xffffffffu, r1, 1));
        r1 = fmaxf(r1, __shfl_xor_sync(0xffffffffu, r1, 2));
        if (lc == 0) { Ps[row0 * 68 + 64 + kh] = r0; Ps[row1 * 68 + 64 + kh] = r1; }
        __syncthreads();
        float rm0 = fmaxf(Ps[row0 * 68 + 64], Ps[row0 * 68 + 65]);
        float rm1 = fmaxf(Ps[row1 * 68 + 64], Ps[row1 * 68 + 65]);

        // ---- softmax; write tf32-rounded P bits ----
        float mn0 = fmaxf(mcur0, rm0), mn1 = fmaxf(mcur1, rm1);
        float f0 = ex2f(mcur0 - mn0), f1 = ex2f(mcur1 - mn1);
        mcur0 = mn0; mcur1 = mn1;
        lcur0 *= f0; lcur1 *= f1;
        float s0 = 0.0f, s1 = 0.0f;
#pragma unroll
        for (int nb = 0; nb < 4; nb++) {
            float p00 = ex2f(sacc[nb][0] - mn0), p01 = ex2f(sacc[nb][1] - mn0);
            float p10 = ex2f(sacc[nb][2] - mn1), p11 = ex2f(sacc[nb][3] - mn1);
            s0 += p00 + p01; s1 += p10 + p11;
            int col = kh * 32 + nb * 8 + 2 * lc;
            *(uint2*)&PsU[row0 * 68 + col] = make_uint2(f2tf(p00), f2tf(p01));
            *(uint2*)&PsU[row1 * 68 + col] = make_uint2(f2tf(p10), f2tf(p11));
        }
        lcur0 += s0; lcur1 += s1;
#pragma unroll
        for (int nb = 0; nb < 8; nb++) {
            oacc[nb][0] *= f0; oacc[nb][1] *= f0;
            oacc[nb][2] *= f1; oacc[nb][3] *= f1;
        }
        __syncthreads();

        // ---- P @ V ----
#pragma unroll
        for (int kc = 0; kc < 8; kc++) {
            uint32_t ap[4];
            ap[0] = PsU[row0 * 68 + kc * 8 + lc];
            ap[1] = PsU[row1 * 68 + kc * 8 + lc];
            ap[2] = PsU[row0 * 68 + kc * 8 + lc + 4];
            ap[3] = PsU[row1 * 68 + kc * 8 + lc + 4];
#pragma unroll
            for (int nb = 0; nb < 8; nb++) {
                uint2 bv = VF2[((kh * 8 + kc) * 8 + nb) * 32 + lane];
                mma_tf32(oacc[nb], ap, (const uint32_t*)&bv);
            }
        }
        __syncthreads();   // frees K/V buffer + Ps for next tile
    }

    // ---- epilogue: merge l via Ps cols 66/67, direct gmem writes ----
    lcur0 += __shfl_xor_sync(0xffffffffu, lcur0, 1);
    lcur0 += __shfl_xor_sync(0xffffffffu, lcur0, 2);
    lcur1 += __shfl_xor_sync(0xffffffffu, lcur1, 1);
    lcur1 += __shfl_xor_sync(0xffffffffu, lcur1, 2);
    if (lc == 0) { Ps[row0 * 68 + 66 + kh] = lcur0; Ps[row1 * 68 + 66 + kh] = lcur1; }
    __syncthreads();
    float li0 = 1.0f / (Ps[row0 * 68 + 66] + Ps[row0 * 68 + 67]);
    float li1 = 1.0f / (Ps[row1 * 68 + 66] + Ps[row1 * 68 + 67]);

    float* ob0 = out + ((size_t)(b * NS + q0 + lr) * NHQ + hk * NG + h) * ND + kh * 64;
    float* ob1 = out + ((size_t)(b * NS + q0 + lr + 8) * NHQ + hk * NG + h) * ND + kh * 64;
#pragma unroll
    for (int nb = 0; nb < 8; nb++) {
        int col = nb * 8 + 2 * lc;
        *(float2*)&ob0[col] = make_float2(oacc[nb][0] * li0, oacc[nb][1] * li0);
        *(float2*)&ob1[col] = make_float2(oacc[nb][2] * li1, oacc[nb][3] * li1);
    }
}

// ---------------------------------------------------------------------------
extern "C" void kernel_launch(void* const* d_in, const int* in_sizes, int n_in,
                              void* d_out, int out_size) {
    const float* q   = (const float*)d_in[0];
    const float* k   = (const float*)d_in[1];
    const float* v   = (const float*)d_in[2];
    const int*   pos = (const int*)d_in[3];
    float* out = (float*)d_out;

    dim3 gp(NTILES, NHK, NB);
    prep_kernel<<<gp, 256>>>(k, v, pos);

    const int smem = SMEM_FLOATS * 4;
    cudaFuncSetAttribute(attn_kernel,
                         cudaFuncAttributeMaxDynamicSharedMemorySize, smem);
    dim3 ga(NS / 16, NHK, NB);
    attn_kernel<<<ga, 256, smem>>>(q, pos, out);
}

// round 14
// speedup vs baseline: 2.2220x; 1.6315x over previous
#include <cuda_runtime.h>
#include <cuda_fp16.h>
#include <math.h>
#include <stdint.h>

#define NB 2
#define NS 2048
#define NHQ 32
#define NHK 8
#define ND 128
#define NG 4
#define WIN 1024
#define NTILES 32

// fp16 fragment-packed per-64-key tiles: [b][hk][tile][8192 halves = 16KB]
__device__ __half g_kt[(size_t)NB * NHK * NTILES * 8192];
__device__ __half g_vt[(size_t)NB * NHK * NTILES * 8192];

__device__ __forceinline__ float ex2f(float x) {
    float r; asm("ex2.approx.ftz.f32 %0,%1;" : "=f"(r) : "f"(x)); return r;
}
__device__ __forceinline__ uint32_t pack_h2(float a, float b) {
    __half2 h = __floats2half2_rn(a, b);
    return *(uint32_t*)&h;
}
__device__ __forceinline__ void mma_f16(float* d, const uint32_t* a, const uint32_t* b) {
    asm volatile(
        "mma.sync.aligned.m16n8k16.row.col.f32.f16.f16.f32 "
        "{%0,%1,%2,%3},{%4,%5,%6,%7},{%8,%9},{%0,%1,%2,%3};"
        : "+f"(d[0]), "+f"(d[1]), "+f"(d[2]), "+f"(d[3])
        : "r"(a[0]), "r"(a[1]), "r"(a[2]), "r"(a[3]), "r"(b[0]), "r"(b[1]));
}
__device__ __forceinline__ uint32_t cvta(const void* p) {
    return (uint32_t)__cvta_generic_to_shared(p);
}
__device__ __forceinline__ void cpa(uint32_t d, const void* s) {
    asm volatile("cp.async.cg.shared.global [%0],[%1],16;" :: "r"(d), "l"(s));
}
#define COMMIT() asm volatile("cp.async.commit_group;")
#define WAIT1()  asm volatile("cp.async.wait_group 1;")

// smem byte offsets
#define QF_B 0          /* 16KB: Q A-frags */
#define KF_B 16384      /* 2 x 16KB */
#define VF_B 49152      /* 2 x 16KB */
#define PS_B 81920      /* 64 x 36 words = 9216B (P tile) */
#define ME_B 91136      /* 256 floats exchange */
#define SMEM_B 92160    /* x2 CTAs = 180KB */

// fragment index helpers (half index within a tile)
__device__ __forceinline__ int qfrag_h(int r, int d) {
    int h = r >> 4, rr = r & 15, c = d >> 4, dd = d & 15;
    int lane = (rr & 7) * 4 + ((dd >> 1) & 3);
    int j = ((rr >> 3) & 1) + 2 * ((dd >> 3) & 1);
    return (((h * 8 + c) * 32) + lane) * 8 + j * 2 + (dd & 1);
}
__device__ __forceinline__ int kfrag_h(int kl, int d) {
    int kh = kl >> 5, krow = kl & 31, nb = krow >> 3, n = krow & 7;
    int c = d >> 4, dd = d & 15;
    int lane = n * 4 + ((dd >> 1) & 3);
    return ((((kh * 8 + c) * 4 + nb) * 32) + lane) * 4 + ((dd >> 3) & 1) * 2 + (dd & 1);
}
__device__ __forceinline__ int vfrag_h(int kl, int d) {
    int kc = kl >> 4, kk = kl & 15;
    int kh = d >> 6, nb = (d >> 3) & 7, n = d & 7;
    int lane = n * 4 + ((kk >> 1) & 3);
    return ((((kh * 4 + kc) * 8 + nb) * 32) + lane) * 4 + ((kk >> 3) & 1) * 2 + (kk & 1);
}

// ---------------------------------------------------------------------------
__global__ void prep_kernel(const float* __restrict__ key,
                            const float* __restrict__ value,
                            const int* __restrict__ pos) {
    const int tile = blockIdx.x, hk = blockIdx.y, b = blockIdx.z;
    const int k0 = tile * 64, tid = threadIdx.x;
    const size_t tb = ((size_t)(b * NHK + hk) * NTILES + tile) * 8192;

#pragma unroll
    for (int i = 0; i < 16; i++) {
        int idx = tid + i * 256;
        int kl = idx >> 6, dp = idx & 63;
        float ps = (float)pos[b * NS + k0 + kl];
        float invf = powf(10000.0f, -((float)dp) / 64.0f);
        float s, c; sincosf(ps * invf, &s, &c);
        const float* kp = key + ((size_t)(b * NS + k0 + kl) * NHK + hk) * ND;
        float x1 = kp[dp], x2 = kp[dp + 64];
        g_kt[tb + kfrag_h(kl, dp)]      = __float2half_rn(x1 * c - x2 * s);
        g_kt[tb + kfrag_h(kl, dp + 64)] = __float2half_rn(x2 * c + x1 * s);
    }
#pragma unroll
    for (int i = 0; i < 32; i++) {
        int idx = tid + i * 256;
        int kl = idx >> 7, d = idx & 127;
        float val = value[((size_t)(b * NS + k0 + kl) * NHK + hk) * ND + d];
        g_vt[tb + vfrag_h(kl, d)] = __float2half_rn(val);
    }
}

// ---------------------------------------------------------------------------
// attention: block=(16q, hk, b), 256 thr, 2 CTAs/SM, K/V double-buffered.
// warp=(h=w&3, kh=w>>2). QK: keys kh*32..+31. PV: dims kh*64..+63.
// ---------------------------------------------------------------------------
__global__ void __launch_bounds__(256, 2)
attn_kernel(const float* __restrict__ query, const int* __restrict__ pos,
            float* __restrict__ out) {
    extern __shared__ char smc[];
    const uint4* QF4 = (const uint4*)(smc + QF_B);
    uint32_t*    PsU = (uint32_t*)(smc + PS_B);   // 64 rows x 36 words
    float*       ME  = (float*)(smc + ME_B);

    const int qt = blockIdx.x, hk = blockIdx.y, b = blockIdx.z;
    const int q0 = qt * 16, tid = threadIdx.x;
    const int w = tid >> 5, lane = tid & 31;
    const int h = w & 3, kh = w >> 2;
    const int lr = lane >> 2, lc = lane & 3;
    const float CF = 1.4426950408889634f * 0.08838834764831845f;

    int jmin = q0 - (WIN - 1); if (jmin < 0) jmin = 0; jmin &= ~63;
    const int nt = (q0 + 15 - jmin) / 64 + 1;
    const size_t kbase = (size_t)(b * NHK + hk) * NTILES * 8192;
    const uint32_t smb = cvta(smc);

    // tile 0 -> buf0 (overlaps with Q rope below)
    {
        const char* ks = (const char*)(g_kt + kbase + (size_t)(jmin >> 6) * 8192);
        const char* vs = (const char*)(g_vt + kbase + (size_t)(jmin >> 6) * 8192);
#pragma unroll
        for (int i = 0; i < 4; i++) {
            cpa(smb + KF_B + tid * 16 + i * 4096, ks + tid * 16 + i * 4096);
            cpa(smb + VF_B + tid * 16 + i * 4096, vs + tid * 16 + i * 4096);
        }
        COMMIT();
    }

    // sincos table in VF buf1 region (floats; tile0 goes to buf0 only)
    float* SC = (float*)(smc + VF_B + 16384);
#pragma unroll
    for (int i = 0; i < 4; i++) {
        int idx = tid + i * 256;
        int qi = idx >> 6, dp = idx & 63;
        float ps = (float)pos[b * NS + q0 + qi];
        float invf = powf(10000.0f, -((float)dp) / 64.0f);
        float s, c; sincosf(ps * invf, &s, &c);
        SC[idx] = c; SC[1024 + idx] = s;
    }
    __syncthreads();
    // rope + scale + round Q -> fp16 A-frags in QF
    __half* QFh = (__half*)(smc + QF_B);
#pragma unroll
    for (int i = 0; i < 16; i++) {
        int idx = tid + i * 256;
        int row = idx >> 6, dp = idx & 63;
        int qi = row & 15, hh = row >> 4;
        const float* qp = query + ((size_t)(b * NS + q0 + qi) * NHQ + (hk * NG + hh)) * ND;
        float x1 = qp[dp], x2 = qp[dp + 64];
        float c = SC[qi * 64 + dp], s = SC[1024 + qi * 64 + dp];
        QFh[qfrag_h(row, dp)]      = __float2half_rn((x1 * c - x2 * s) * CF);
        QFh[qfrag_h(row, dp + 64)] = __float2half_rn((x2 * c + x1 * s) * CF);
    }
    __syncthreads();   // Q done; VF buf1 (sincos) free for prefetch

    float oacc[8][4];
#pragma unroll
    for (int nb = 0; nb < 8; nb++)
#pragma unroll
        for (int e = 0; e < 4; e++) oacc[nb][e] = 0.0f;
    float mcur0 = -1e30f, mcur1 = -1e30f, lcur0 = 0.0f, lcur1 = 0.0f;

    const int row0 = h * 16 + lr, row1 = row0 + 8;
    const int i0 = q0 + lr, i1 = i0 + 8;

    for (int t = 0; t < nt; t++) {
        const int k0 = jmin + t * 64, buf = t & 1;

        // prefetch t+1 into the other buffer (its readers finished at end of t-1)
        if (t + 1 < nt) {
            const char* ks = (const char*)(g_kt + kbase + (size_t)((k0 >> 6) + 1) * 8192);
            const char* vs = (const char*)(g_vt + kbase + (size_t)((k0 >> 6) + 1) * 8192);
            uint32_t kd = smb + KF_B + (1 - buf) * 16384;
            uint32_t vd = smb + VF_B + (1 - buf) * 16384;
#pragma unroll
            for (int i = 0; i < 4; i++) {
                cpa(kd + tid * 16 + i * 4096, ks + tid * 16 + i * 4096);
                cpa(vd + tid * 16 + i * 4096, vs + tid * 16 + i * 4096);
            }
        }
        COMMIT();
        WAIT1();
        __syncthreads();

        const uint2* KF2 = (const uint2*)(smc + KF_B + buf * 16384);
        const uint2* VF2 = (const uint2*)(smc + VF_B + buf * 16384);

        // ---- QK^T: 8 k16-chunks x 4 n8 ----
        float sacc[4][4];
#pragma unroll
        for (int nb = 0; nb < 4; nb++)
#pragma unroll
            for (int e = 0; e < 4; e++) sacc[nb][e] = 0.0f;
#pragma unroll
        for (int c = 0; c < 8; c++) {
            uint4 qv = QF4[(h * 8 + c) * 32 + lane];
#pragma unroll
            for (int nb = 0; nb < 4; nb++) {
                uint2 kv = KF2[((kh * 8 + c) * 4 + nb) * 32 + lane];
                mma_f16(sacc[nb], (const uint32_t*)&qv, (const uint32_t*)&kv);
            }
        }

        // ---- mask ----
        if (!((k0 + 63 <= q0) && (q0 + 15 - k0 < WIN))) {
#pragma unroll
            for (int nb = 0; nb < 4; nb++) {
                int j0 = k0 + kh * 32 + nb * 8 + 2 * lc;
                if (j0 > i0     || i0 - j0 >= WIN)     sacc[nb][0] = -1e38f;
                if (j0 + 1 > i0 || i0 - j0 - 1 >= WIN) sacc[nb][1] = -1e38f;
                if (j0 > i1     || i1 - j0 >= WIN)     sacc[nb][2] = -1e38f;
                if (j0 + 1 > i1 || i1 - j0 - 1 >= WIN) sacc[nb][3] = -1e38f;
            }
        }

        // ---- half-row max -> exchange via ME ----
        float r0 = -1e38f, r1 = -1e38f;
#pragma unroll
        for (int nb = 0; nb < 4; nb++) {
            r0 = fmaxf(r0, fmaxf(sacc[nb][0], sacc[nb][1]));
            r1 = fmaxf(r1, fmaxf(sacc[nb][2], sacc[nb][3]));
        }
        r0 = fmaxf(r0, __shfl_xor_sync(0xffffffffu, r0, 1));
        r0 = fmaxf(r0, __shfl_xor_sync(0xffffffffu, r0, 2));
        r1 = fmaxf(r1, __shfl_xor_sync(0xffffffffu, r1, 1));
        r1 = fmaxf(r1, __shfl_xor_sync(0xffffffffu, r1, 2));
        if (lc == 0) { ME[kh * 64 + row0] = r0; ME[kh * 64 + row1] = r1; }
        __syncthreads();
        float rm0 = fmaxf(ME[row0], ME[64 + row0]);
        float rm1 = fmaxf(ME[row1], ME[64 + row1]);

        // ---- softmax; write fp16 P pairs ----
        float mn0 = fmaxf(mcur0, rm0), mn1 = fmaxf(mcur1, rm1);
        float f0 = ex2f(mcur0 - mn0), f1 = ex2f(mcur1 - mn1);
        mcur0 = mn0; mcur1 = mn1;
        lcur0 *= f0; lcur1 *= f1;
        float s0 = 0.0f, s1 = 0.0f;
#pragma unroll
        for (int nb = 0; nb < 4; nb++) {
            float p00 = ex2f(sacc[nb][0] - mn0), p01 = ex2f(sacc[nb][1] - mn0);
            float p10 = ex2f(sacc[nb][2] - mn1), p11 = ex2f(sacc[nb][3] - mn1);
            s0 += p00 + p01; s1 += p10 + p11;
            int wcol = kh * 16 + nb * 4 + lc;
            PsU[row0 * 36 + wcol] = pack_h2(p00, p01);
            PsU[row1 * 36 + wcol] = pack_h2(p10, p11);
        }
        lcur0 += s0; lcur1 += s1;
#pragma unroll
        for (int nb = 0; nb < 8; nb++) {
            oacc[nb][0] *= f0; oacc[nb][1] *= f0;
            oacc[nb][2] *= f1; oacc[nb][3] *= f1;
        }
        __syncthreads();

        // ---- P @ V: 4 k16-chunks x 8 n8 ----
#pragma unroll
        for (int kc = 0; kc < 4; kc++) {
            uint32_t ap[4];
            ap[0] = PsU[row0 * 36 + kc * 8 + lc];
            ap[1] = PsU[row1 * 36 + kc * 8 + lc];
            ap[2] = PsU[row0 * 36 + kc * 8 + lc + 4];
            ap[3] = PsU[row1 * 36 + kc * 8 + lc + 4];
#pragma unroll
            for (int nb = 0; nb < 8; nb++) {
                uint2 bv = VF2[((kh * 4 + kc) * 8 + nb) * 32 + lane];
                mma_f16(oacc[nb], ap, (const uint32_t*)&bv);
            }
        }
        __syncthreads();   // tile t consumed; next iter may overwrite buf^1
    }

    // ---- epilogue ----
    lcur0 += __shfl_xor_sync(0xffffffffu, lcur0, 1);
    lcur0 += __shfl_xor_sync(0xffffffffu, lcur0, 2);
    lcur1 += __shfl_xor_sync(0xffffffffu, lcur1, 1);
    lcur1 += __shfl_xor_sync(0xffffffffu, lcur1, 2);
    if (lc == 0) { ME[128 + kh * 64 + row0] = lcur0; ME[128 + kh * 64 + row1] = lcur1; }
    __syncthreads();
    float li0 = 1.0f / (ME[128 + row0] + ME[192 + row0]);
    float li1 = 1.0f / (ME[128 + row1] + ME[192 + row1]);

    float* ob0 = out + ((size_t)(b * NS + q0 + lr) * NHQ + hk * NG + h) * ND + kh * 64;
    float* ob1 = out + ((size_t)(b * NS + q0 + lr + 8) * NHQ + hk * NG + h) * ND + kh * 64;
#pragma unroll
    for (int nb = 0; nb < 8; nb++) {
        int col = nb * 8 + 2 * lc;
        *(float2*)&ob0[col] = make_float2(oacc[nb][0] * li0, oacc[nb][1] * li0);
        *(float2*)&ob1[col] = make_float2(oacc[nb][2] * li1, oacc[nb][3] * li1);
    }
}

// ---------------------------------------------------------------------------
extern "C" void kernel_launch(void* const* d_in, const int* in_sizes, int n_in,
                              void* d_out, int out_size) {
    const float* q   = (const float*)d_in[0];
    const float* k   = (const float*)d_in[1];
    const float* v   = (const float*)d_in[2];
    const int*   pos = (const int*)d_in[3];
    float* out = (float*)d_out;

    dim3 gp(NTILES, NHK, NB);
    prep_kernel<<<gp, 256>>>(k, v, pos);

    cudaFuncSetAttribute(attn_kernel,
                         cudaFuncAttributeMaxDynamicSharedMemorySize, SMEM_B);
    dim3 ga(NS / 16, NHK, NB);
    attn_kernel<<<ga, 256, SMEM_B>>>(q, pos, out);
}

// round 15
// speedup vs baseline: 2.3954x; 1.0781x over previous
#include <cuda_runtime.h>
#include <cuda_fp16.h>
#include <math.h>
#include <stdint.h>

#define NB 2
#define NS 2048
#define NHQ 32
#define NHK 8
#define ND 128
#define NG 4
#define WIN 1024
#define NTILES 32

// fp16 fragment-packed per-64-key tiles: [b][hk][tile][8192 halves = 16KB]
__device__ __half g_kt[(size_t)NB * NHK * NTILES * 8192];
__device__ __half g_vt[(size_t)NB * NHK * NTILES * 8192];

__device__ __forceinline__ float ex2f(float x) {
    float r; asm("ex2.approx.ftz.f32 %0,%1;" : "=f"(r) : "f"(x)); return r;
}
__device__ __forceinline__ uint32_t pack_h2(float a, float b) {
    __half2 h = __floats2half2_rn(a, b);
    return *(uint32_t*)&h;
}
__device__ __forceinline__ void mma_f16(float* d, const uint32_t* a, const uint32_t* b) {
    asm volatile(
        "mma.sync.aligned.m16n8k16.row.col.f32.f16.f16.f32 "
        "{%0,%1,%2,%3},{%4,%5,%6,%7},{%8,%9},{%0,%1,%2,%3};"
        : "+f"(d[0]), "+f"(d[1]), "+f"(d[2]), "+f"(d[3])
        : "r"(a[0]), "r"(a[1]), "r"(a[2]), "r"(a[3]), "r"(b[0]), "r"(b[1]));
}
__device__ __forceinline__ uint32_t cvta(const void* p) {
    return (uint32_t)__cvta_generic_to_shared(p);
}
__device__ __forceinline__ void cpa(uint32_t d, const void* s) {
    asm volatile("cp.async.cg.shared.global [%0],[%1],16;" :: "r"(d), "l"(s));
}
#define COMMIT() asm volatile("cp.async.commit_group;")
#define WAITG(n) asm volatile("cp.async.wait_group %0;" :: "n"(n))

// smem byte offsets (per CTA: 102400 B; x2 CTAs = 204800 <= 227KB)
#define QF_B 0          /* 32KB: Q A-frags, 128 rows */
#define KF_B 32768      /* 2 x 16KB (double-buffered) */
#define VF_B 65536      /* 16KB (single-buffered) */
#define PS_B 81920      /* 128 x 36 words = 18432B (P tile; sincos staging) */
#define ME_B 100352     /* 512 floats exchange */
#define SMEM_B 102400

// fragment index helpers
__device__ __forceinline__ int qfrag_h(int r, int d) {  // r in [0,128): h*32+qi
    int h = r >> 5, qi = r & 31, mt = qi >> 4, rr = qi & 15;
    int c = d >> 4, dd = d & 15;
    int lane = (rr & 7) * 4 + ((dd >> 1) & 3);
    int j = ((rr >> 3) & 1) + 2 * ((dd >> 3) & 1);
    return ((((h * 2 + mt) * 8 + c) * 32) + lane) * 8 + j * 2 + (dd & 1);
}
__device__ __forceinline__ int kfrag_h(int kl, int d) {
    int kh = kl >> 5, krow = kl & 31, nb = krow >> 3, n = krow & 7;
    int c = d >> 4, dd = d & 15;
    int lane = n * 4 + ((dd >> 1) & 3);
    return ((((kh * 8 + c) * 4 + nb) * 32) + lane) * 4 + ((dd >> 3) & 1) * 2 + (dd & 1);
}
__device__ __forceinline__ int vfrag_h(int kl, int d) {
    int kc = kl >> 4, kk = kl & 15;
    int kh = d >> 6, nb = (d >> 3) & 7, n = d & 7;
    int lane = n * 4 + ((kk >> 1) & 3);
    return ((((kh * 4 + kc) * 8 + nb) * 32) + lane) * 4 + ((kk >> 3) & 1) * 2 + (kk & 1);
}

// ---------------------------------------------------------------------------
__global__ void prep_kernel(const float* __restrict__ key,
                            const float* __restrict__ value,
                            const int* __restrict__ pos) {
    const int tile = blockIdx.x, hk = blockIdx.y, b = blockIdx.z;
    const int k0 = tile * 64, tid = threadIdx.x;
    const size_t tb = ((size_t)(b * NHK + hk) * NTILES + tile) * 8192;

#pragma unroll
    for (int i = 0; i < 16; i++) {
        int idx = tid + i * 256;
        int kl = idx >> 6, dp = idx & 63;
        float ps = (float)pos[b * NS + k0 + kl];
        float invf = powf(10000.0f, -((float)dp) / 64.0f);
        float s, c; sincosf(ps * invf, &s, &c);
        const float* kp = key + ((size_t)(b * NS + k0 + kl) * NHK + hk) * ND;
        float x1 = kp[dp], x2 = kp[dp + 64];
        g_kt[tb + kfrag_h(kl, dp)]      = __float2half_rn(x1 * c - x2 * s);
        g_kt[tb + kfrag_h(kl, dp + 64)] = __float2half_rn(x2 * c + x1 * s);
    }
#pragma unroll
    for (int i = 0; i < 32; i++) {
        int idx = tid + i * 256;
        int kl = idx >> 7, d = idx & 127;
        float val = value[((size_t)(b * NS + k0 + kl) * NHK + hk) * ND + d];
        g_vt[tb + vfrag_h(kl, d)] = __float2half_rn(val);
    }
}

// ---------------------------------------------------------------------------
// attention: block=(32q, hk, b), 256 thr, 2 CTAs/SM.
// warp=(h=w&3, kh=w>>2). QK: keys kh*32..+31, 2 M-tiles. PV: dims kh*64..+63.
// ---------------------------------------------------------------------------
__global__ void __launch_bounds__(256, 2)
attn_kernel(const float* __restrict__ query, const int* __restrict__ pos,
            float* __restrict__ out) {
    extern __shared__ char smc[];
    const uint4* QF4 = (const uint4*)(smc + QF_B);
    uint32_t*    PsU = (uint32_t*)(smc + PS_B);   // 128 rows x 36 words
    float*       ME  = (float*)(smc + ME_B);

    const int qt = blockIdx.x, hk = blockIdx.y, b = blockIdx.z;
    const int q0 = qt * 32, tid = threadIdx.x;
    const int w = tid >> 5, lane = tid & 31;
    const int h = w & 3, kh = w >> 2;
    const int lr = lane >> 2, lc = lane & 3;
    const float CF = 1.4426950408889634f * 0.08838834764831845f;

    int jmin = q0 - (WIN - 1); if (jmin < 0) jmin = 0; jmin &= ~63;
    const int nt = (q0 + 31 - jmin) / 64 + 1;
    const size_t kbase = (size_t)(b * NHK + hk) * NTILES * 8192;
    const uint32_t smb = cvta(smc);

    // prologue: K(0) then V(0), separate groups
    {
        const char* ks = (const char*)(g_kt + kbase + (size_t)(jmin >> 6) * 8192);
        const char* vs = (const char*)(g_vt + kbase + (size_t)(jmin >> 6) * 8192);
#pragma unroll
        for (int i = 0; i < 4; i++) cpa(smb + KF_B + tid * 16 + i * 4096, ks + tid * 16 + i * 4096);
        COMMIT();
#pragma unroll
        for (int i = 0; i < 4; i++) cpa(smb + VF_B + tid * 16 + i * 4096, vs + tid * 16 + i * 4096);
        COMMIT();
    }

    // sincos staging in PS region (32q x 64 = 2048 cos + 2048 sin)
    float* SC = (float*)(smc + PS_B);
#pragma unroll
    for (int i = 0; i < 8; i++) {
        int idx = tid + i * 256;
        int qi = idx >> 6, dp = idx & 63;
        float ps = (float)pos[b * NS + q0 + qi];
        float invf = powf(10000.0f, -((float)dp) / 64.0f);
        float s, c; sincosf(ps * invf, &s, &c);
        SC[idx] = c; SC[2048 + idx] = s;
    }
    __syncthreads();
    // rope + scale + round Q -> fp16 A-frags (128 rows)
    __half* QFh = (__half*)(smc + QF_B);
#pragma unroll
    for (int i = 0; i < 32; i++) {
        int idx = tid + i * 256;
        int row = idx >> 6, dp = idx & 63;
        int qi = row & 31, hh = row >> 5;
        const float* qp = query + ((size_t)(b * NS + q0 + qi) * NHQ + (hk * NG + hh)) * ND;
        float x1 = qp[dp], x2 = qp[dp + 64];
        float c = SC[qi * 64 + dp], s = SC[2048 + qi * 64 + dp];
        QFh[qfrag_h(row, dp)]      = __float2half_rn((x1 * c - x2 * s) * CF);
        QFh[qfrag_h(row, dp + 64)] = __float2half_rn((x2 * c + x1 * s) * CF);
    }
    __syncthreads();   // Q + PS free

    float oacc[2][8][4];
#pragma unroll
    for (int mt = 0; mt < 2; mt++)
#pragma unroll
        for (int nb = 0; nb < 8; nb++)
#pragma unroll
            for (int e = 0; e < 4; e++) oacc[mt][nb][e] = 0.0f;
    float mcur[2][2] = {{-1e30f,-1e30f},{-1e30f,-1e30f}};
    float lcur[2][2] = {{0.f,0.f},{0.f,0.f}};

    for (int t = 0; t < nt; t++) {
        const int k0 = jmin + t * 64, buf = t & 1;

        // group A_t: V(t) (empty for t=0 — prologue loaded V0)
        if (t > 0) {
            const char* vs = (const char*)(g_vt + kbase + (size_t)(k0 >> 6) * 8192);
#pragma unroll
            for (int i = 0; i < 4; i++) cpa(smb + VF_B + tid * 16 + i * 4096, vs + tid * 16 + i * 4096);
        }
        COMMIT();
        // group B_t: K(t+1) (empty at tail)
        if (t + 1 < nt) {
            const char* ks = (const char*)(g_kt + kbase + (size_t)((k0 >> 6) + 1) * 8192);
            uint32_t kd = smb + KF_B + (1 - buf) * 16384;
#pragma unroll
            for (int i = 0; i < 4; i++) cpa(kd + tid * 16 + i * 4096, ks + tid * 16 + i * 4096);
        }
        COMMIT();
        WAITG(2);          // K(t) (and all older) complete
        __syncthreads();

        const uint2* KF2 = (const uint2*)(smc + KF_B + buf * 16384);

        // ---- QK^T: 8 k16-chunks x 4 n8 x 2 m-tiles ----
        float sacc[2][4][4];
#pragma unroll
        for (int mt = 0; mt < 2; mt++)
#pragma unroll
            for (int nb = 0; nb < 4; nb++)
#pragma unroll
                for (int e = 0; e < 4; e++) sacc[mt][nb][e] = 0.0f;
#pragma unroll
        for (int c = 0; c < 8; c++) {
            uint4 qv0 = QF4[((h * 2 + 0) * 8 + c) * 32 + lane];
            uint4 qv1 = QF4[((h * 2 + 1) * 8 + c) * 32 + lane];
#pragma unroll
            for (int nb = 0; nb < 4; nb++) {
                uint2 kv = KF2[((kh * 8 + c) * 4 + nb) * 32 + lane];
                mma_f16(sacc[0][nb], (const uint32_t*)&qv0, (const uint32_t*)&kv);
                mma_f16(sacc[1][nb], (const uint32_t*)&qv1, (const uint32_t*)&kv);
            }
        }

        // ---- mask ----
        if (!((k0 + 63 <= q0) && (q0 + 31 - k0 < WIN))) {
#pragma unroll
            for (int mt = 0; mt < 2; mt++) {
                int ia = q0 + mt * 16 + lr, ib = ia + 8;
#pragma unroll
                for (int nb = 0; nb < 4; nb++) {
                    int j0 = k0 + kh * 32 + nb * 8 + 2 * lc;
                    if (j0 > ia     || ia - j0 >= WIN)     sacc[mt][nb][0] = -1e38f;
                    if (j0 + 1 > ia || ia - j0 - 1 >= WIN) sacc[mt][nb][1] = -1e38f;
                    if (j0 > ib     || ib - j0 >= WIN)     sacc[mt][nb][2] = -1e38f;
                    if (j0 + 1 > ib || ib - j0 - 1 >= WIN) sacc[mt][nb][3] = -1e38f;
                }
            }
        }

        // ---- half-row maxes -> exchange via ME ----
#pragma unroll
        for (int mt = 0; mt < 2; mt++) {
            float r0 = -1e38f, r1 = -1e38f;
#pragma unroll
            for (int nb = 0; nb < 4; nb++) {
                r0 = fmaxf(r0, fmaxf(sacc[mt][nb][0], sacc[mt][nb][1]));
                r1 = fmaxf(r1, fmaxf(sacc[mt][nb][2], sacc[mt][nb][3]));
            }
            r0 = fmaxf(r0, __shfl_xor_sync(0xffffffffu, r0, 1));
            r0 = fmaxf(r0, __shfl_xor_sync(0xffffffffu, r0, 2));
            r1 = fmaxf(r1, __shfl_xor_sync(0xffffffffu, r1, 1));
            r1 = fmaxf(r1, __shfl_xor_sync(0xffffffffu, r1, 2));
            if (lc == 0) {
                ME[kh * 128 + h * 32 + mt * 16 + lr]     = r0;
                ME[kh * 128 + h * 32 + mt * 16 + 8 + lr] = r1;
            }
        }
        __syncthreads();

        // ---- softmax; write fp16 P pairs ----
#pragma unroll
        for (int mt = 0; mt < 2; mt++) {
            int r0i = h * 32 + mt * 16 + lr, r1i = r0i + 8;
            float rm0 = fmaxf(ME[r0i], ME[128 + r0i]);
            float rm1 = fmaxf(ME[r1i], ME[128 + r1i]);
            float mn0 = fmaxf(mcur[mt][0], rm0), mn1 = fmaxf(mcur[mt][1], rm1);
            float f0 = ex2f(mcur[mt][0] - mn0), f1 = ex2f(mcur[mt][1] - mn1);
            mcur[mt][0] = mn0; mcur[mt][1] = mn1;
            lcur[mt][0] *= f0; lcur[mt][1] *= f1;
            float s0 = 0.0f, s1 = 0.0f;
#pragma unroll
            for (int nb = 0; nb < 4; nb++) {
                float p00 = ex2f(sacc[mt][nb][0] - mn0), p01 = ex2f(sacc[mt][nb][1] - mn0);
                float p10 = ex2f(sacc[mt][nb][2] - mn1), p11 = ex2f(sacc[mt][nb][3] - mn1);
                s0 += p00 + p01; s1 += p10 + p11;
                int wcol = kh * 16 + nb * 4 + lc;
                PsU[r0i * 36 + wcol] = pack_h2(p00, p01);
                PsU[r1i * 36 + wcol] = pack_h2(p10, p11);
            }
            lcur[mt][0] += s0; lcur[mt][1] += s1;
#pragma unroll
            for (int nb = 0; nb < 8; nb++) {
                oacc[mt][nb][0] *= f0; oacc[mt][nb][1] *= f0;
                oacc[mt][nb][2] *= f1; oacc[mt][nb][3] *= f1;
            }
        }
        WAITG(1);          // V(t) complete (K(t+1) may still fly)
        __syncthreads();   // P + V visible

        // ---- P @ V: 4 k16-chunks x 8 n8 x 2 m-tiles ----
        const uint2* VF2 = (const uint2*)(smc + VF_B);
#pragma unroll
        for (int kc = 0; kc < 4; kc++) {
            uint32_t ap[2][4];
#pragma unroll
            for (int mt = 0; mt < 2; mt++) {
                int r0i = h * 32 + mt * 16 + lr, r1i = r0i + 8;
                ap[mt][0] = PsU[r0i * 36 + kc * 8 + lc];
                ap[mt][1] = PsU[r1i * 36 + kc * 8 + lc];
                ap[mt][2] = PsU[r0i * 36 + kc * 8 + lc + 4];
                ap[mt][3] = PsU[r1i * 36 + kc * 8 + lc + 4];
            }
#pragma unroll
            for (int nb = 0; nb < 8; nb++) {
                uint2 bv = VF2[((kh * 4 + kc) * 8 + nb) * 32 + lane];
                mma_f16(oacc[0][nb], ap[0], (const uint32_t*)&bv);
                mma_f16(oacc[1][nb], ap[1], (const uint32_t*)&bv);
            }
        }
        __syncthreads();   // tile t consumed (V buffer + P free)
    }

    // ---- epilogue: merge l across kh via ME, direct writes ----
#pragma unroll
    for (int mt = 0; mt < 2; mt++) {
        float l0 = lcur[mt][0], l1 = lcur[mt][1];
        l0 += __shfl_xor_sync(0xffffffffu, l0, 1);
        l0 += __shfl_xor_sync(0xffffffffu, l0, 2);
        l1 += __shfl_xor_sync(0xffffffffu, l1, 1);
        l1 += __shfl_xor_sync(0xffffffffu, l1, 2);
        if (lc == 0) {
            ME[kh * 128 + h * 32 + mt * 16 + lr]     = l0;
            ME[kh * 128 + h * 32 + mt * 16 + 8 + lr] = l1;
        }
    }
    __syncthreads();
#pragma unroll
    for (int mt = 0; mt < 2; mt++) {
        int r0i = h * 32 + mt * 16 + lr, r1i = r0i + 8;
        float li0 = 1.0f / (ME[r0i] + ME[128 + r0i]);
        float li1 = 1.0f / (ME[r1i] + ME[128 + r1i]);
        float* ob0 = out + ((size_t)(b * NS + q0 + mt * 16 + lr) * NHQ + hk * NG + h) * ND + kh * 64;
        float* ob1 = out + ((size_t)(b * NS + q0 + mt * 16 + 8 + lr) * NHQ + hk * NG + h) * ND + kh * 64;
#pragma unroll
        for (int nb = 0; nb < 8; nb++) {
            int col = nb * 8 + 2 * lc;
            *(float2*)&ob0[col] = make_float2(oacc[mt][nb][0] * li0, oacc[mt][nb][1] * li0);
            *(float2*)&ob1[col] = make_float2(oacc[mt][nb][2] * li1, oacc[mt][nb][3] * li1);
        }
    }
}

// ---------------------------------------------------------------------------
extern "C" void kernel_launch(void* const* d_in, const int* in_sizes, int n_in,
                              void* d_out, int out_size) {
    const float* q   = (const float*)d_in[0];
    const float* k   = (const float*)d_in[1];
    const float* v   = (const float*)d_in[2];
    const int*   pos = (const int*)d_in[3];
    float* out = (float*)d_out;

    dim3 gp(NTILES, NHK, NB);
    prep_kernel<<<gp, 256>>>(k, v, pos);

    cudaFuncSetAttribute(attn_kernel,
                         cudaFuncAttributeMaxDynamicSharedMemorySize, SMEM_B);
    dim3 ga(NS / 32, NHK, NB);
    attn_kernel<<<ga, 256, SMEM_B>>>(q, pos, out);
}

// round 16
// speedup vs baseline: 2.6644x; 1.1123x over previous
#include <cuda_runtime.h>
#include <cuda_fp16.h>
#include <math.h>
#include <stdint.h>

#define NB 2
#define NS 2048
#define NHQ 32
#define NHK 8
#define ND 128
#define NG 4
#define WIN 1024
#define NTILES 32

// fp16 fragment-packed per-64-key tiles: [b][hk][tile][8192 halves = 16KB]
__device__ __half g_kt[(size_t)NB * NHK * NTILES * 8192];
__device__ __half g_vt[(size_t)NB * NHK * NTILES * 8192];

__device__ __forceinline__ float ex2f(float x) {
    float r; asm("ex2.approx.ftz.f32 %0,%1;" : "=f"(r) : "f"(x)); return r;
}
__device__ __forceinline__ uint32_t pack_h2(float a, float b) {
    __half2 h = __floats2half2_rn(a, b);
    return *(uint32_t*)&h;
}
__device__ __forceinline__ void mma_f16(float* d, const uint32_t* a, const uint32_t* b) {
    asm volatile(
        "mma.sync.aligned.m16n8k16.row.col.f32.f16.f16.f32 "
        "{%0,%1,%2,%3},{%4,%5,%6,%7},{%8,%9},{%0,%1,%2,%3};"
        : "+f"(d[0]), "+f"(d[1]), "+f"(d[2]), "+f"(d[3])
        : "r"(a[0]), "r"(a[1]), "r"(a[2]), "r"(a[3]), "r"(b[0]), "r"(b[1]));
}
__device__ __forceinline__ uint32_t cvta(const void* p) {
    return (uint32_t)__cvta_generic_to_shared(p);
}
__device__ __forceinline__ void cpa(uint32_t d, const void* s) {
    asm volatile("cp.async.cg.shared.global [%0],[%1],16;" :: "r"(d), "l"(s));
}
#define COMMIT() asm volatile("cp.async.commit_group;")
#define WAITG(n) asm volatile("cp.async.wait_group %0;" :: "n"(n))

// smem byte offsets (per CTA: 102400 B; x2 CTAs = 204800 <= 227KB)
#define QF_B 0          /* 32KB: Q A-frags, 128 rows */
#define KF_B 32768      /* 2 x 16KB (double-buffered) */
#define VF_B 65536      /* 16KB (single-buffered) */
#define PS_B 81920      /* 128 x 36 words = 18432B (P tile; sincos staging) */
#define ME_B 100352     /* 512 floats: powf table / l exchange */
#define SMEM_B 102400

// fragment index helpers
__device__ __forceinline__ int qfrag_h(int r, int d) {  // r in [0,128): h*32+qi
    int h = r >> 5, qi = r & 31, mt = qi >> 4, rr = qi & 15;
    int c = d >> 4, dd = d & 15;
    int lane = (rr & 7) * 4 + ((dd >> 1) & 3);
    int j = ((rr >> 3) & 1) + 2 * ((dd >> 3) & 1);
    return ((((h * 2 + mt) * 8 + c) * 32) + lane) * 8 + j * 2 + (dd & 1);
}
__device__ __forceinline__ int kfrag_h(int kl, int d) {
    int kh = kl >> 5, krow = kl & 31, nb = krow >> 3, n = krow & 7;
    int c = d >> 4, dd = d & 15;
    int lane = n * 4 + ((dd >> 1) & 3);
    return ((((kh * 8 + c) * 4 + nb) * 32) + lane) * 4 + ((dd >> 3) & 1) * 2 + (dd & 1);
}
__device__ __forceinline__ int vfrag_h(int kl, int d) {
    int kc = kl >> 4, kk = kl & 15;
    int kh = d >> 6, nb = (d >> 3) & 7, n = d & 7;
    int lane = n * 4 + ((kk >> 1) & 3);
    return ((((kh * 4 + kc) * 8 + nb) * 32) + lane) * 4 + ((kk >> 3) & 1) * 2 + (kk & 1);
}

// ---------------------------------------------------------------------------
__global__ void prep_kernel(const float* __restrict__ key,
                            const float* __restrict__ value,
                            const int* __restrict__ pos) {
    const int tile = blockIdx.x, hk = blockIdx.y, b = blockIdx.z;
    const int k0 = tile * 64, tid = threadIdx.x;
    const size_t tb = ((size_t)(b * NHK + hk) * NTILES + tile) * 8192;
    __shared__ float inv[64];
    if (tid < 64) inv[tid] = powf(10000.0f, -((float)tid) / 64.0f);
    __syncthreads();

#pragma unroll
    for (int i = 0; i < 16; i++) {
        int idx = tid + i * 256;
        int kl = idx >> 6, dp = idx & 63;
        float ps = (float)pos[b * NS + k0 + kl];
        float s, c; sincosf(ps * inv[dp], &s, &c);
        const float* kp = key + ((size_t)(b * NS + k0 + kl) * NHK + hk) * ND;
        float x1 = kp[dp], x2 = kp[dp + 64];
        g_kt[tb + kfrag_h(kl, dp)]      = __float2half_rn(x1 * c - x2 * s);
        g_kt[tb + kfrag_h(kl, dp + 64)] = __float2half_rn(x2 * c + x1 * s);
    }
#pragma unroll
    for (int i = 0; i < 32; i++) {
        int idx = tid + i * 256;
        int kl = idx >> 7, d = idx & 127;
        float val = value[((size_t)(b * NS + k0 + kl) * NHK + hk) * ND + d];
        g_vt[tb + vfrag_h(kl, d)] = __float2half_rn(val);
    }
}

// ---------------------------------------------------------------------------
// attention: block=(32q, hk, b), 256 thr, 2 CTAs/SM. Static-max softmax:
// p = exp2(s) raw (Cauchy-Schwarz bounds s <= 16.3 -> no overflow), out = O/l.
// warp=(h=w&3, kh=w>>2). QK: keys kh*32..+31, 2 M-tiles. PV: dims kh*64..+63.
// ---------------------------------------------------------------------------
__global__ void __launch_bounds__(256, 2)
attn_kernel(const float* __restrict__ query, const int* __restrict__ pos,
            float* __restrict__ out) {
    extern __shared__ char smc[];
    const uint4* QF4 = (const uint4*)(smc + QF_B);
    uint32_t*    PsU = (uint32_t*)(smc + PS_B);   // 128 rows x 36 words
    float*       ME  = (float*)(smc + ME_B);

    const int qt = blockIdx.x, hk = blockIdx.y, b = blockIdx.z;
    const int q0 = qt * 32, tid = threadIdx.x;
    const int w = tid >> 5, lane = tid & 31;
    const int h = w & 3, kh = w >> 2;
    const int lr = lane >> 2, lc = lane & 3;
    const float CF = 1.4426950408889634f * 0.08838834764831845f;

    int jmin = q0 - (WIN - 1); if (jmin < 0) jmin = 0; jmin &= ~63;
    const int nt = (q0 + 31 - jmin) / 64 + 1;
    const size_t kbase = (size_t)(b * NHK + hk) * NTILES * 8192;
    const uint32_t smb = cvta(smc);

    // prologue: K(0) then V(0), separate groups
    {
        const char* ks = (const char*)(g_kt + kbase + (size_t)(jmin >> 6) * 8192);
        const char* vs = (const char*)(g_vt + kbase + (size_t)(jmin >> 6) * 8192);
#pragma unroll
        for (int i = 0; i < 4; i++) cpa(smb + KF_B + tid * 16 + i * 4096, ks + tid * 16 + i * 4096);
        COMMIT();
#pragma unroll
        for (int i = 0; i < 4; i++) cpa(smb + VF_B + tid * 16 + i * 4096, vs + tid * 16 + i * 4096);
        COMMIT();
    }

    // inv-freq table (ME) then sincos staging (PS region)
    if (tid < 64) ME[tid] = powf(10000.0f, -((float)tid) / 64.0f);
    __syncthreads();
    float* SC = (float*)(smc + PS_B);
#pragma unroll
    for (int i = 0; i < 8; i++) {
        int idx = tid + i * 256;
        int qi = idx >> 6, dp = idx & 63;
        float ps = (float)pos[b * NS + q0 + qi];
        float s, c; sincosf(ps * ME[dp], &s, &c);
        SC[idx] = c; SC[2048 + idx] = s;
    }
    __syncthreads();
    // rope + scale + round Q -> fp16 A-frags (128 rows)
    __half* QFh = (__half*)(smc + QF_B);
#pragma unroll
    for (int i = 0; i < 32; i++) {
        int idx = tid + i * 256;
        int row = idx >> 6, dp = idx & 63;
        int qi = row & 31, hh = row >> 5;
        const float* qp = query + ((size_t)(b * NS + q0 + qi) * NHQ + (hk * NG + hh)) * ND;
        float x1 = qp[dp], x2 = qp[dp + 64];
        float c = SC[qi * 64 + dp], s = SC[2048 + qi * 64 + dp];
        QFh[qfrag_h(row, dp)]      = __float2half_rn((x1 * c - x2 * s) * CF);
        QFh[qfrag_h(row, dp + 64)] = __float2half_rn((x2 * c + x1 * s) * CF);
    }
    __syncthreads();   // Q ready; PS free

    float oacc[2][8][4];
#pragma unroll
    for (int mt = 0; mt < 2; mt++)
#pragma unroll
        for (int nb = 0; nb < 8; nb++)
#pragma unroll
            for (int e = 0; e < 4; e++) oacc[mt][nb][e] = 0.0f;
    float lcur[2][2] = {{0.f,0.f},{0.f,0.f}};

    for (int t = 0; t < nt; t++) {
        const int k0 = jmin + t * 64, buf = t & 1;

        // group A_t: V(t) (empty for t=0 — prologue loaded V0)
        if (t > 0) {
            const char* vs = (const char*)(g_vt + kbase + (size_t)(k0 >> 6) * 8192);
#pragma unroll
            for (int i = 0; i < 4; i++) cpa(smb + VF_B + tid * 16 + i * 4096, vs + tid * 16 + i * 4096);
        }
        COMMIT();
        // group B_t: K(t+1) (empty at tail)
        if (t + 1 < nt) {
            const char* ks = (const char*)(g_kt + kbase + (size_t)((k0 >> 6) + 1) * 8192);
            uint32_t kd = smb + KF_B + (1 - buf) * 16384;
#pragma unroll
            for (int i = 0; i < 4; i++) cpa(kd + tid * 16 + i * 4096, ks + tid * 16 + i * 4096);
        }
        COMMIT();
        WAITG(2);          // K(t) (and older) complete
        __syncthreads();

        const uint2* KF2 = (const uint2*)(smc + KF_B + buf * 16384);

        // ---- QK^T: 8 k16-chunks x 4 n8 x 2 m-tiles ----
        float sacc[2][4][4];
#pragma unroll
        for (int mt = 0; mt < 2; mt++)
#pragma unroll
            for (int nb = 0; nb < 4; nb++)
#pragma unroll
                for (int e = 0; e < 4; e++) sacc[mt][nb][e] = 0.0f;
#pragma unroll
        for (int c = 0; c < 8; c++) {
            uint4 qv0 = QF4[((h * 2 + 0) * 8 + c) * 32 + lane];
            uint4 qv1 = QF4[((h * 2 + 1) * 8 + c) * 32 + lane];
#pragma unroll
            for (int nb = 0; nb < 4; nb++) {
                uint2 kv = KF2[((kh * 8 + c) * 4 + nb) * 32 + lane];
                mma_f16(sacc[0][nb], (const uint32_t*)&qv0, (const uint32_t*)&kv);
                mma_f16(sacc[1][nb], (const uint32_t*)&qv1, (const uint32_t*)&kv);
            }
        }

        // ---- mask (masked -> -1e38 -> ex2f = 0) ----
        if (!((k0 + 63 <= q0) && (q0 + 31 - k0 < WIN))) {
#pragma unroll
            for (int mt = 0; mt < 2; mt++) {
                int ia = q0 + mt * 16 + lr, ib = ia + 8;
#pragma unroll
                for (int nb = 0; nb < 4; nb++) {
                    int j0 = k0 + kh * 32 + nb * 8 + 2 * lc;
                    if (j0 > ia     || ia - j0 >= WIN)     sacc[mt][nb][0] = -1e38f;
                    if (j0 + 1 > ia || ia - j0 - 1 >= WIN) sacc[mt][nb][1] = -1e38f;
                    if (j0 > ib     || ib - j0 >= WIN)     sacc[mt][nb][2] = -1e38f;
                    if (j0 + 1 > ib || ib - j0 - 1 >= WIN) sacc[mt][nb][3] = -1e38f;
                }
            }
        }

        // ---- static-max softmax: p = exp2(s); write fp16 P; accumulate l ----
#pragma unroll
        for (int mt = 0; mt < 2; mt++) {
            int r0i = h * 32 + mt * 16 + lr, r1i = r0i + 8;
            float s0 = 0.0f, s1 = 0.0f;
#pragma unroll
            for (int nb = 0; nb < 4; nb++) {
                float p00 = ex2f(sacc[mt][nb][0]), p01 = ex2f(sacc[mt][nb][1]);
                float p10 = ex2f(sacc[mt][nb][2]), p11 = ex2f(sacc[mt][nb][3]);
                s0 += p00 + p01; s1 += p10 + p11;
                int wcol = kh * 16 + nb * 4 + lc;
                PsU[r0i * 36 + wcol] = pack_h2(p00, p01);
                PsU[r1i * 36 + wcol] = pack_h2(p10, p11);
            }
            lcur[mt][0] += s0; lcur[mt][1] += s1;
        }
        WAITG(1);          // V(t) complete (K(t+1) may still fly)
        __syncthreads();   // P + V visible

        // ---- P @ V: 4 k16-chunks x 8 n8 x 2 m-tiles ----
        const uint2* VF2 = (const uint2*)(smc + VF_B);
#pragma unroll
        for (int kc = 0; kc < 4; kc++) {
            uint32_t ap[2][4];
#pragma unroll
            for (int mt = 0; mt < 2; mt++) {
                int r0i = h * 32 + mt * 16 + lr, r1i = r0i + 8;
                ap[mt][0] = PsU[r0i * 36 + kc * 8 + lc];
                ap[mt][1] = PsU[r1i * 36 + kc * 8 + lc];
                ap[mt][2] = PsU[r0i * 36 + kc * 8 + lc + 4];
                ap[mt][3] = PsU[r1i * 36 + kc * 8 + lc + 4];
            }
#pragma unroll
            for (int nb = 0; nb < 8; nb++) {
                uint2 bv = VF2[((kh * 4 + kc) * 8 + nb) * 32 + lane];
                mma_f16(oacc[0][nb], ap[0], (const uint32_t*)&bv);
                mma_f16(oacc[1][nb], ap[1], (const uint32_t*)&bv);
            }
        }
        __syncthreads();   // tile t consumed (V buffer + P free)
    }

    // ---- epilogue: merge l across kh via ME, direct writes ----
#pragma unroll
    for (int mt = 0; mt < 2; mt++) {
        float l0 = lcur[mt][0], l1 = lcur[mt][1];
        l0 += __shfl_xor_sync(0xffffffffu, l0, 1);
        l0 += __shfl_xor_sync(0xffffffffu, l0, 2);
        l1 += __shfl_xor_sync(0xffffffffu, l1, 1);
        l1 += __shfl_xor_sync(0xffffffffu, l1, 2);
        if (lc == 0) {
            ME[kh * 128 + h * 32 + mt * 16 + lr]     = l0;
            ME[kh * 128 + h * 32 + mt * 16 + 8 + lr] = l1;
        }
    }
    __syncthreads();
#pragma unroll
    for (int mt = 0; mt < 2; mt++) {
        int r0i = h * 32 + mt * 16 + lr, r1i = r0i + 8;
        float li0 = 1.0f / (ME[r0i] + ME[128 + r0i]);
        float li1 = 1.0f / (ME[r1i] + ME[128 + r1i]);
        float* ob0 = out + ((size_t)(b * NS + q0 + mt * 16 + lr) * NHQ + hk * NG + h) * ND + kh * 64;
        float* ob1 = out + ((size_t)(b * NS + q0 + mt * 16 + 8 + lr) * NHQ + hk * NG + h) * ND + kh * 64;
#pragma unroll
        for (int nb = 0; nb < 8; nb++) {
            int col = nb * 8 + 2 * lc;
            *(float2*)&ob0[col] = make_float2(oacc[mt][nb][0] * li0, oacc[mt][nb][1] * li0);
            *(float2*)&ob1[col] = make_float2(oacc[mt][nb][2] * li1, oacc[mt][nb][3] * li1);
        }
    }
}

// ---------------------------------------------------------------------------
extern "C" void kernel_launch(void* const* d_in, const int* in_sizes, int n_in,
                              void* d_out, int out_size) {
    const float* q   = (const float*)d_in[0];
    const float* k   = (const float*)d_in[1];
    const float* v   = (const float*)d_in[2];
    const int*   pos = (const int*)d_in[3];
    float* out = (float*)d_out;

    dim3 gp(NTILES, NHK, NB);
    prep_kernel<<<gp, 256>>>(k, v, pos);

    cudaFuncSetAttribute(attn_kernel,
                         cudaFuncAttributeMaxDynamicSharedMemorySize, SMEM_B);
    dim3 ga(NS / 32, NHK, NB);
    attn_kernel<<<ga, 256, SMEM_B>>>(q, pos, out);
}